// round 6
// baseline (speedup 1.0000x reference)
#include <cuda_runtime.h>

// ---------------- grid constants ---------------------------------------------
#define G      96
#define NCELLS (G*G*G)            // 884736
#define NB     (NCELLS/1024)      // 864 (exact)
#define LO     (-6.0f)
#define HCELL  (0.125f)           // 12/96
#define INVH   (8.0f)
#define RMAX   3

// ---------------- static scratch (no allocations) ----------------------------
__device__ int g_cnt[2][NCELLS];      // [0]=gt grid, [1]=pred grid
__device__ int g_off[2][NCELLS];      // exclusive-scan cell starts
__device__ int g_cur[2][NCELLS];      // alloc cursor -> cell ends after scatter
__device__ int g_bsum[2][NB];

__device__ float4 g_sgt4[32768];  __device__ int g_sgti[32768];
__device__ float4 g_spr4[8192];   __device__ int g_spri[8192];

__device__ unsigned long long g_best1[8192];   // per pred: key | gt idx
__device__ unsigned long long g_best2[32768];  // per gt:   key | pred idx
__device__ int   g_flag1[8192], g_flag2[32768];
__device__ int   g_nflag[2];
__device__ float g_partial[256];

// ---------------- helpers ----------------------------------------------------
__device__ __forceinline__ int clampi(int v, int lo, int hi) {
    return v < lo ? lo : (v > hi ? hi : v);
}
__device__ __forceinline__ int cell_id(float x, float y, float z) {
    int cx = clampi((int)((x - LO) * INVH), 0, G - 1);
    int cy = clampi((int)((y - LO) * INVH), 0, G - 1);
    int cz = clampi((int)((z - LO) * INVH), 0, G - 1);
    return (cz * G + cy) * G + cx;
}
// monotone float -> sortable unsigned
__device__ __forceinline__ unsigned fkey(float f) {
    unsigned u = __float_as_uint(f);
    return u ^ ((unsigned)((int)u >> 31) | 0x80000000u);
}

// ---------------- build: zero, count, scan, scatter --------------------------
__global__ void zero_kernel() {
    int i = blockIdx.x * blockDim.x + threadIdx.x;
    if (i < NCELLS) { g_cnt[0][i] = 0; g_cnt[1][i] = 0; }
    if (i < 2) g_nflag[i] = 0;
}

__global__ void count_kernel(const float* __restrict__ pp,
                             const float* __restrict__ gp, int N, int M) {
    int i = blockIdx.x * blockDim.x + threadIdx.x;
    if (i < M) atomicAdd(&g_cnt[0][cell_id(gp[3*i], gp[3*i+1], gp[3*i+2])], 1);
    if (i < N) atomicAdd(&g_cnt[1][cell_id(pp[3*i], pp[3*i+1], pp[3*i+2])], 1);
}

__global__ void scan1_kernel() {     // per-1024-block exclusive scan
    __shared__ int sh[1024];
    int a = blockIdx.y, tid = threadIdx.x;
    int gi = blockIdx.x * 1024 + tid;
    int v = g_cnt[a][gi];
    sh[tid] = v; __syncthreads();
    for (int o = 1; o < 1024; o <<= 1) {
        int t = (tid >= o) ? sh[tid - o] : 0;
        __syncthreads(); sh[tid] += t; __syncthreads();
    }
    g_off[a][gi] = sh[tid] - v;
    if (tid == 1023) g_bsum[a][blockIdx.x] = sh[tid];
}

__global__ void scan2_kernel() {     // scan the 864 block sums
    __shared__ int sh[1024];
    int a = blockIdx.x, tid = threadIdx.x;
    int v = (tid < NB) ? g_bsum[a][tid] : 0;
    sh[tid] = v; __syncthreads();
    for (int o = 1; o < 1024; o <<= 1) {
        int t = (tid >= o) ? sh[tid - o] : 0;
        __syncthreads(); sh[tid] += t; __syncthreads();
    }
    if (tid < NB) g_bsum[a][tid] = sh[tid] - v;
}

__global__ void scan3_kernel() {     // add block offsets, init cursors
    int a = blockIdx.y;
    int gi = blockIdx.x * 1024 + threadIdx.x;
    int o = g_off[a][gi] + g_bsum[a][blockIdx.x];
    g_off[a][gi] = o;
    g_cur[a][gi] = o;
}

__global__ void scatter_kernel(const float* __restrict__ pp,
                               const float* __restrict__ gp, int N, int M) {
    int i = blockIdx.x * blockDim.x + threadIdx.x;
    if (i < M) {
        float x = gp[3*i], y = gp[3*i+1], z = gp[3*i+2];
        int pos = atomicAdd(&g_cur[0][cell_id(x, y, z)], 1);
        g_sgt4[pos] = make_float4(x, y, z, x*x + y*y + z*z);
        g_sgti[pos] = i;
    }
    if (i < N) {
        float x = pp[3*i], y = pp[3*i+1], z = pp[3*i+2];
        int pos = atomicAdd(&g_cur[1][cell_id(x, y, z)], 1);
        g_spr4[pos] = make_float4(x, y, z, x*x + y*y + z*z);
        g_spri[pos] = i;
    }
}

// ---------------- exact NN: expanding shells ---------------------------------
__device__ __forceinline__ void scan_cell(int a, int c,
    const float4* __restrict__ c4, const int* __restrict__ ci,
    float qx, float qy, float qz,
    unsigned long long& bk, float& bs)
{
    int s = g_off[a][c];
    int e = g_cur[a][c];
    for (int k = s; k < e; k++) {
        float4 cc = c4[k];
        float sc = fmaf(qx, cc.x, fmaf(qy, cc.y, fmaf(qz, cc.z, cc.w)));
        unsigned long long key = ((unsigned long long)fkey(sc) << 32)
                               | (unsigned)ci[k];
        if (key < bk) bk = key;
        bs = fminf(bs, sc);
    }
}

// DIR==0: pred queries vs gt grid(a=0) -> g_best1
// DIR==1: gt   queries vs pred grid(a=1) -> g_best2
template <int DIR>
__global__ __launch_bounds__(128) void query_kernel(const float* __restrict__ qp,
                                                    int NQ) {
    int qi = blockIdx.x * blockDim.x + threadIdx.x;
    if (qi >= NQ) return;
    float px = qp[3*qi], py = qp[3*qi+1], pz = qp[3*qi+2];
    float qq = px*px + py*py + pz*pz;
    float qx = -2.0f * px, qy = -2.0f * py, qz = -2.0f * pz;
    int cx = clampi((int)((px - LO) * INVH), 0, G - 1);
    int cy = clampi((int)((py - LO) * INVH), 0, G - 1);
    int cz = clampi((int)((pz - LO) * INVH), 0, G - 1);

    const float4* c4 = DIR ? g_spr4 : g_sgt4;
    const int*    ci = DIR ? g_spri : g_sgti;

    unsigned long long bk = ~0ULL;
    float bs = 3.4e38f;
    bool resolved = false;

    for (int r = 0; r <= RMAX; r++) {
        int xlo = max(cx - r, 0), xhi = min(cx + r, G - 1);
        int ylo = max(cy - r, 0), yhi = min(cy + r, G - 1);
        int zlo = max(cz - r, 0), zhi = min(cz + r, G - 1);
        for (int z = zlo; z <= zhi; z++) {
            bool zf = (z == cz - r) || (z == cz + r);
            for (int y = ylo; y <= yhi; y++) {
                int rowb = (z * G + y) * G;
                if (zf || y == cy - r || y == cy + r) {
                    for (int x = xlo; x <= xhi; x++)
                        scan_cell(DIR, rowb + x, c4, ci, qx, qy, qz, bk, bs);
                } else {
                    if (cx - r >= 0) scan_cell(DIR, rowb + cx - r, c4, ci, qx, qy, qz, bk, bs);
                    if (cx + r <  G) scan_cell(DIR, rowb + cx + r, c4, ci, qx, qy, qz, bk, bs);
                }
            }
        }
        float rh = r * HCELL;
        // any unvisited point is >= r*h away (query inside its own cell)
        if (bs + qq <= rh * rh) { resolved = true; break; }
    }

    if (resolved) {
        if (DIR) g_best2[qi] = bk; else g_best1[qi] = bk;
    } else {
        int s = atomicAdd(&g_nflag[DIR], 1);
        if (DIR) g_flag2[s] = qi; else g_flag1[s] = qi;
    }
}

// ---------------- brute-force fallback: warp per flagged query ---------------
template <int DIR>
__global__ __launch_bounds__(256) void fallback_kernel(const float* __restrict__ qp) {
    int gt = blockIdx.x * blockDim.x + threadIdx.x;
    int w = gt >> 5, lane = gt & 31;
    int nwarps = (gridDim.x * blockDim.x) >> 5;
    int nf = g_nflag[DIR];
    const int NC      = DIR ? 8192   : 32768;
    const float4* c4  = DIR ? g_spr4 : g_sgt4;
    const int*    ci  = DIR ? g_spri : g_sgti;
    const int*    fl  = DIR ? g_flag2 : g_flag1;

    for (int f = w; f < nf; f += nwarps) {
        int qi = fl[f];
        float qx = -2.0f * qp[3*qi], qy = -2.0f * qp[3*qi+1], qz = -2.0f * qp[3*qi+2];
        unsigned long long bk = ~0ULL;
        for (int k = lane; k < NC; k += 32) {
            float4 cc = c4[k];
            float sc = fmaf(qx, cc.x, fmaf(qy, cc.y, fmaf(qz, cc.z, cc.w)));
            unsigned long long key = ((unsigned long long)fkey(sc) << 32)
                                   | (unsigned)ci[k];
            if (key < bk) bk = key;
        }
        for (int o = 16; o; o >>= 1) {
            unsigned long long v = __shfl_down_sync(0xFFFFFFFFu, bk, o);
            if (v < bk) bk = v;
        }
        if (lane == 0) { if (DIR) g_best2[qi] = bk; else g_best1[qi] = bk; }
    }
}

// ---------------- loss: deterministic two-stage reduction --------------------
__global__ __launch_bounds__(256) void loss_stage1(const float* __restrict__ pn,
                                                   const float* __restrict__ gn,
                                                   int N, int M) {
    const int tid = threadIdx.x;
    const int gid = blockIdx.x * blockDim.x + tid;
    const int stride = gridDim.x * blockDim.x;
    float s1 = 0.f, s2 = 0.f;
    for (int i = gid; i < N; i += stride) {
        int j = (int)(unsigned)g_best1[i];
        s1 += pn[3*i] * gn[3*j] + pn[3*i+1] * gn[3*j+1] + pn[3*i+2] * gn[3*j+2];
    }
    for (int j = gid; j < M; j += stride) {
        int i = (int)(unsigned)g_best2[j];
        s2 += gn[3*j] * pn[3*i] + gn[3*j+1] * pn[3*i+1] + gn[3*j+2] * pn[3*i+2];
    }
    __shared__ float r1[256], r2[256];
    r1[tid] = s1; r2[tid] = s2;
    __syncthreads();
    for (int o = 128; o > 0; o >>= 1) {
        if (tid < o) { r1[tid] += r1[tid + o]; r2[tid] += r2[tid + o]; }
        __syncthreads();
    }
    if (tid == 0) { g_partial[blockIdx.x] = r1[0]; g_partial[128 + blockIdx.x] = r2[0]; }
}

__global__ void finish_kernel(float* __restrict__ out, float invN, float invM) {
    __shared__ float sa[128], sb[128];
    int t = threadIdx.x;
    sa[t] = g_partial[t];
    sb[t] = g_partial[128 + t];
    __syncthreads();
    for (int o = 64; o > 0; o >>= 1) {
        if (t < o) { sa[t] += sa[t + o]; sb[t] += sb[t + o]; }
        __syncthreads();
    }
    if (t == 0) out[0] = 2.0f - sa[0] * invN - sb[0] * invM;
}

// ---------------- launch -----------------------------------------------------
extern "C" void kernel_launch(void* const* d_in, const int* in_sizes, int n_in,
                              void* d_out, int out_size) {
    const float* pred_pts = (const float*)d_in[0];
    const float* pred_nrm = (const float*)d_in[1];
    const float* gt_pts   = (const float*)d_in[2];
    const float* gt_nrm   = (const float*)d_in[3];
    float* out = (float*)d_out;

    const int N = in_sizes[0] / 3;   // 8192
    const int M = in_sizes[2] / 3;   // 32768
    const int mx = (N > M) ? N : M;

    zero_kernel<<<NB, 1024>>>();
    count_kernel<<<(mx + 255) / 256, 256>>>(pred_pts, gt_pts, N, M);
    scan1_kernel<<<dim3(NB, 2), 1024>>>();
    scan2_kernel<<<2, 1024>>>();
    scan3_kernel<<<dim3(NB, 2), 1024>>>();
    scatter_kernel<<<(mx + 255) / 256, 256>>>(pred_pts, gt_pts, N, M);

    query_kernel<0><<<(N + 127) / 128, 128>>>(pred_pts, N);
    query_kernel<1><<<(M + 127) / 128, 128>>>(gt_pts, M);
    fallback_kernel<0><<<64, 256>>>(pred_pts);
    fallback_kernel<1><<<64, 256>>>(gt_pts);

    loss_stage1<<<128, 256>>>(pred_nrm, gt_nrm, N, M);
    finish_kernel<<<1, 128>>>(out, 1.0f / (float)N, 1.0f / (float)M);
}

// round 7
// speedup vs baseline: 1.7346x; 1.7346x over previous
#include <cuda_runtime.h>

#define TPB     256
#define PT      128      // preds per block tile
#define GCHUNK  128      // gts per smem chunk
#define STRIPS  16       // gt strips (blockIdx.y)

// ---------------- static scratch (no allocations) ----------------------------
__device__ float4             g_pr4[8192];    // (-2x, -2y, -2z, |p|^2)
__device__ float4             g_gt4[32768];   // ( x,   y,   z, |g|^2)
__device__ unsigned long long g_best1[8192];  // per pred: key | gt idx
__device__ unsigned long long g_best2[32768]; // per gt:   key | pred idx
__device__ float              g_partial[256];

// monotone float -> sortable unsigned (handles negatives)
__device__ __forceinline__ unsigned fkey(float f) {
    unsigned u = __float_as_uint(f);
    return u ^ ((unsigned)((int)u >> 31) | 0x80000000u);
}

// ---------------- prep: pack float4, init winners ----------------------------
__global__ void prep_kernel(const float* __restrict__ pp,
                            const float* __restrict__ gp, int N, int M) {
    int i = blockIdx.x * blockDim.x + threadIdx.x;
    if (i < N) {
        float x = pp[3*i], y = pp[3*i+1], z = pp[3*i+2];
        g_pr4[i] = make_float4(-2.0f*x, -2.0f*y, -2.0f*z, x*x + y*y + z*z);
        g_best1[i] = ~0ULL;
    }
    if (i < M) {
        float x = gp[3*i], y = gp[3*i+1], z = gp[3*i+2];
        g_gt4[i] = make_float4(x, y, z, x*x + y*y + z*z);
        g_best2[i] = ~0ULL;
    }
}

// ---------------- fused bidirectional argmin ---------------------------------
// Each pair (i,j) evaluated ONCE:
//   core = -2 p_i . g_j
//   row score rs = core + |g_j|^2   (argmin over j for fixed i)
//   col score cs = core + |p_i|^2   (argmin over i for fixed j)
__global__ __launch_bounds__(TPB, 2) void fused_kernel(int N, int M) {
    __shared__ float4             sgt[GCHUNK];
    __shared__ unsigned long long sred[GCHUNK];   // col winners / row winners

    const int tx = threadIdx.x & 15;
    const int ty = threadIdx.x >> 4;
    const int pred0 = blockIdx.x * PT;
    const int strip = M / STRIPS;                 // 2048
    const int gt0 = blockIdx.y * strip;
    const int nchunks = strip / GCHUNK;           // 16

    // resident pred tile: 8 points per thread, in registers
    float4 pr[8];
    float  rbest[8];
    int    ridx[8];
#pragma unroll
    for (int ii = 0; ii < 8; ii++) {
        pr[ii]    = g_pr4[pred0 + ty * 8 + ii];
        rbest[ii] = 3.4e38f;
        ridx[ii]  = 0;
    }

    for (int c = 0; c < nchunks; c++) {
        __syncthreads();                          // protect sred/sgt reuse
        if (threadIdx.x < GCHUNK)
            sgt[threadIdx.x] = g_gt4[gt0 + c * GCHUNK + threadIdx.x];
        else
            sred[threadIdx.x - GCHUNK] = ~0ULL;
        __syncthreads();

        float4 gr[8];
        int    jg[8];
        float  cbest[8];
        int    cidx[8];
#pragma unroll
        for (int jj = 0; jj < 8; jj++) {
            gr[jj]    = sgt[jj * 16 + tx];        // j ascending in jj
            jg[jj]    = gt0 + c * GCHUNK + jj * 16 + tx;
            cbest[jj] = 3.4e38f;
            cidx[jj]  = 0;
        }

#pragma unroll
        for (int ii = 0; ii < 8; ii++) {          // i ascending -> col tie-break
            const float ux = pr[ii].x, uy = pr[ii].y, uz = pr[ii].z, pp = pr[ii].w;
            const int   ig = pred0 + ty * 8 + ii;
#pragma unroll
            for (int jj = 0; jj < 8; jj++) {      // j ascending -> row tie-break
                float core = fmaf(ux, gr[jj].x, fmaf(uy, gr[jj].y, uz * gr[jj].z));
                float rs = core + gr[jj].w;
                float cs = core + pp;
                bool r = rs < rbest[ii];
                ridx[ii]  = r ? jg[jj] : ridx[ii];
                rbest[ii] = fminf(rbest[ii], rs);
                bool q = cs < cbest[jj];
                cidx[jj]  = q ? ig : cidx[jj];
                cbest[jj] = fminf(cbest[jj], cs);
            }
        }

        // col winners: smem reduce across ty, then one global atomic per gt
#pragma unroll
        for (int jj = 0; jj < 8; jj++) {
            unsigned long long k = ((unsigned long long)fkey(cbest[jj]) << 32)
                                 | (unsigned)cidx[jj];
            atomicMin(&sred[jj * 16 + tx], k);
        }
        __syncthreads();
        if (threadIdx.x < GCHUNK)
            atomicMin(&g_best2[gt0 + c * GCHUNK + threadIdx.x], sred[threadIdx.x]);
    }

    // row winners: smem reduce across tx, then one global atomic per pred
    __syncthreads();
    if (threadIdx.x < PT) sred[threadIdx.x] = ~0ULL;
    __syncthreads();
#pragma unroll
    for (int ii = 0; ii < 8; ii++) {
        unsigned long long k = ((unsigned long long)fkey(rbest[ii]) << 32)
                             | (unsigned)ridx[ii];
        atomicMin(&sred[ty * 8 + ii], k);
    }
    __syncthreads();
    if (threadIdx.x < PT)
        atomicMin(&g_best1[pred0 + threadIdx.x], sred[threadIdx.x]);
}

// ---------------- loss: deterministic two-stage reduction --------------------
__global__ __launch_bounds__(256) void loss_stage1(const float* __restrict__ pn,
                                                   const float* __restrict__ gn,
                                                   int N, int M) {
    const int tid = threadIdx.x;
    const int gid = blockIdx.x * blockDim.x + tid;
    const int stride = gridDim.x * blockDim.x;
    float s1 = 0.f, s2 = 0.f;
    for (int i = gid; i < N; i += stride) {
        int j = (int)(unsigned)g_best1[i];
        s1 += pn[3*i] * gn[3*j] + pn[3*i+1] * gn[3*j+1] + pn[3*i+2] * gn[3*j+2];
    }
    for (int j = gid; j < M; j += stride) {
        int i = (int)(unsigned)g_best2[j];
        s2 += gn[3*j] * pn[3*i] + gn[3*j+1] * pn[3*i+1] + gn[3*j+2] * pn[3*i+2];
    }
    __shared__ float r1[256], r2[256];
    r1[tid] = s1; r2[tid] = s2;
    __syncthreads();
    for (int o = 128; o > 0; o >>= 1) {
        if (tid < o) { r1[tid] += r1[tid + o]; r2[tid] += r2[tid + o]; }
        __syncthreads();
    }
    if (tid == 0) { g_partial[blockIdx.x] = r1[0]; g_partial[128 + blockIdx.x] = r2[0]; }
}

__global__ void finish_kernel(float* __restrict__ out, float invN, float invM) {
    __shared__ float sa[128], sb[128];
    int t = threadIdx.x;
    sa[t] = g_partial[t];
    sb[t] = g_partial[128 + t];
    __syncthreads();
    for (int o = 64; o > 0; o >>= 1) {
        if (t < o) { sa[t] += sa[t + o]; sb[t] += sb[t + o]; }
        __syncthreads();
    }
    if (t == 0) out[0] = 2.0f - sa[0] * invN - sb[0] * invM;
}

// ---------------- launch -----------------------------------------------------
extern "C" void kernel_launch(void* const* d_in, const int* in_sizes, int n_in,
                              void* d_out, int out_size) {
    const float* pred_pts = (const float*)d_in[0];
    const float* pred_nrm = (const float*)d_in[1];
    const float* gt_pts   = (const float*)d_in[2];
    const float* gt_nrm   = (const float*)d_in[3];
    float* out = (float*)d_out;

    const int N = in_sizes[0] / 3;   // 8192
    const int M = in_sizes[2] / 3;   // 32768
    const int mx = (N > M) ? N : M;

    prep_kernel<<<(mx + TPB - 1) / TPB, TPB>>>(pred_pts, gt_pts, N, M);

    dim3 grid(N / PT, STRIPS);       // 64 x 16 = 1024 blocks
    fused_kernel<<<grid, TPB>>>(N, M);

    loss_stage1<<<128, 256>>>(pred_nrm, gt_nrm, N, M);
    finish_kernel<<<1, 128>>>(out, 1.0f / (float)N, 1.0f / (float)M);
}

// round 8
// speedup vs baseline: 2.6170x; 1.5087x over previous
#include <cuda_runtime.h>

#define TPB    128
#define QPB    256          // queries per block (2 per thread)
#define PAIRS  1024         // candidate pairs per smem tile (2048 candidates)
#define GPAIRS 32           // pairs per group (rescan granule)
#define NGRP   (PAIRS / GPAIRS)

// ---------------- static scratch (no allocations) ----------------------------
__device__ float4             g_gxy[16384];   // gt  pairs: (x0,x1,y0,y1)
__device__ float4             g_gzw[16384];   // gt  pairs: (z0,z1,w0,w1)
__device__ float4             g_pxy[4096];    // pred pairs
__device__ float4             g_pzw[4096];
__device__ unsigned long long g_best1[8192];  // per pred: key | gt idx
__device__ unsigned long long g_best2[32768]; // per gt:   key | pred idx
__device__ float              g_partial[256];

// ---------------- packed f32x2 helpers ---------------------------------------
__device__ __forceinline__ unsigned long long splat2(float f) {
    unsigned long long r;
    asm("mov.b64 %0, {%1, %1};" : "=l"(r) : "f"(f));
    return r;
}
__device__ __forceinline__ unsigned long long ffma2(unsigned long long a,
                                                    unsigned long long b,
                                                    unsigned long long c) {
    unsigned long long d;
    asm("fma.rn.f32x2 %0, %1, %2, %3;" : "=l"(d) : "l"(a), "l"(b), "l"(c));
    return d;
}
__device__ __forceinline__ void unpack2(unsigned long long v, float& lo, float& hi) {
    asm("mov.b64 {%0, %1}, %2;" : "=f"(lo), "=f"(hi) : "l"(v));
}
// monotone float -> sortable unsigned (handles negatives)
__device__ __forceinline__ unsigned fkey(float f) {
    unsigned u = __float_as_uint(f);
    return u ^ ((unsigned)((int)u >> 31) | 0x80000000u);
}

// ---------------- prep: paired-SoA pack + winner init ------------------------
__global__ void prep_kernel(const float* __restrict__ pp,
                            const float* __restrict__ gp, int N, int M) {
    int i = blockIdx.x * blockDim.x + threadIdx.x;
    if (i < N) g_best1[i] = ~0ULL;
    if (i < M) g_best2[i] = ~0ULL;
    if (i < N / 2) {
        float x0 = pp[6*i],   y0 = pp[6*i+1], z0 = pp[6*i+2];
        float x1 = pp[6*i+3], y1 = pp[6*i+4], z1 = pp[6*i+5];
        g_pxy[i] = make_float4(x0, x1, y0, y1);
        g_pzw[i] = make_float4(z0, z1, x0*x0 + y0*y0 + z0*z0,
                                       x1*x1 + y1*y1 + z1*z1);
    }
    if (i < M / 2) {
        float x0 = gp[6*i],   y0 = gp[6*i+1], z0 = gp[6*i+2];
        float x1 = gp[6*i+3], y1 = gp[6*i+4], z1 = gp[6*i+5];
        g_gxy[i] = make_float4(x0, x1, y0, y1);
        g_gzw[i] = make_float4(z0, z1, x0*x0 + y0*y0 + z0*z0,
                                       x1*x1 + y1*y1 + z1*z1);
    }
}

// ---------------- NN argmin: min-only pass + group rescan --------------------
// score(q, c) = |c|^2 - 2 q.c   (same chain as validated rounds)
// DIR==0: queries = pred, candidates = gt  -> g_best1
// DIR==1: queries = gt,   candidates = pred -> g_best2
template <int DIR>
__global__ __launch_bounds__(TPB) void nn_kernel(const float* __restrict__ qp) {
    __shared__ ulonglong2 sxy[PAIRS];   // (x0,x1) | (y0,y1)
    __shared__ ulonglong2 szw[PAIRS];   // (z0,z1) | (w0,w1)
    const ulonglong2* gxy = DIR ? (const ulonglong2*)g_pxy : (const ulonglong2*)g_gxy;
    const ulonglong2* gzw = DIR ? (const ulonglong2*)g_pzw : (const ulonglong2*)g_gzw;
    unsigned long long* best = DIR ? g_best2 : g_best1;

    const int pairbase = blockIdx.y * PAIRS;
    for (int t = threadIdx.x; t < PAIRS; t += TPB) {
        sxy[t] = gxy[pairbase + t];
        szw[t] = gzw[pairbase + t];
    }
    __syncthreads();

    const int qA = blockIdx.x * QPB + threadIdx.x;
    const int qB = qA + TPB;
    const unsigned long long Ax = splat2(-2.0f * qp[3*qA]);
    const unsigned long long Ay = splat2(-2.0f * qp[3*qA+1]);
    const unsigned long long Az = splat2(-2.0f * qp[3*qA+2]);
    const unsigned long long Bx = splat2(-2.0f * qp[3*qB]);
    const unsigned long long By = splat2(-2.0f * qp[3*qB+1]);
    const unsigned long long Bz = splat2(-2.0f * qp[3*qB+2]);

    float bmA = 3.4e38f, bmB = 3.4e38f;
    int bgA = 0, bgB = 0;

    for (int g = 0; g < NGRP; g++) {
        const float oA = bmA, oB = bmB;
        const int t0 = g * GPAIRS;
#pragma unroll 8
        for (int t = t0; t < t0 + GPAIRS; t++) {
            ulonglong2 a = sxy[t];
            ulonglong2 b = szw[t];
            unsigned long long sA = ffma2(Ax, a.x, ffma2(Ay, a.y, ffma2(Az, b.x, b.y)));
            unsigned long long sB = ffma2(Bx, a.x, ffma2(By, a.y, ffma2(Bz, b.x, b.y)));
            float a0, a1, c0, c1;
            unpack2(sA, a0, a1);
            unpack2(sB, c0, c1);
            bmA = fminf(bmA, fminf(a0, a1));
            bmB = fminf(bmB, fminf(c0, c1));
        }
        bgA = (bmA < oA) ? g : bgA;   // last group that improved holds the min;
        bgB = (bmB < oB) ? g : bgB;   // equal-later never updates -> first occurrence
    }

    // rescan winning group only (32 pairs, uniform trip count, no divergence);
    // descending scan + odd-before-even overwrite => smallest matching index
    int iA = 0, iB = 0;
    {
        const int t0 = bgA * GPAIRS;
#pragma unroll
        for (int u = GPAIRS - 1; u >= 0; u--) {
            const int t = t0 + u;
            ulonglong2 a = sxy[t], b = szw[t];
            unsigned long long s = ffma2(Ax, a.x, ffma2(Ay, a.y, ffma2(Az, b.x, b.y)));
            float s0, s1; unpack2(s, s0, s1);
            iA = (s1 == bmA) ? 2*t + 1 : iA;
            iA = (s0 == bmA) ? 2*t     : iA;
        }
    }
    {
        const int t0 = bgB * GPAIRS;
#pragma unroll
        for (int u = GPAIRS - 1; u >= 0; u--) {
            const int t = t0 + u;
            ulonglong2 a = sxy[t], b = szw[t];
            unsigned long long s = ffma2(Bx, a.x, ffma2(By, a.y, ffma2(Bz, b.x, b.y)));
            float s0, s1; unpack2(s, s0, s1);
            iB = (s1 == bmB) ? 2*t + 1 : iB;
            iB = (s0 == bmB) ? 2*t     : iB;
        }
    }

    const int cbase = pairbase * 2;   // candidate index base of this tile
    atomicMin(&best[qA], ((unsigned long long)fkey(bmA) << 32) | (unsigned)(cbase + iA));
    atomicMin(&best[qB], ((unsigned long long)fkey(bmB) << 32) | (unsigned)(cbase + iB));
}

// ---------------- loss: deterministic two-stage reduction --------------------
__global__ __launch_bounds__(256) void loss_stage1(const float* __restrict__ pn,
                                                   const float* __restrict__ gn,
                                                   int N, int M) {
    const int tid = threadIdx.x;
    const int gid = blockIdx.x * blockDim.x + tid;
    const int stride = gridDim.x * blockDim.x;
    float s1 = 0.f, s2 = 0.f;
    for (int i = gid; i < N; i += stride) {
        int j = (int)(unsigned)g_best1[i];
        s1 += pn[3*i] * gn[3*j] + pn[3*i+1] * gn[3*j+1] + pn[3*i+2] * gn[3*j+2];
    }
    for (int j = gid; j < M; j += stride) {
        int i = (int)(unsigned)g_best2[j];
        s2 += gn[3*j] * pn[3*i] + gn[3*j+1] * pn[3*i+1] + gn[3*j+2] * pn[3*i+2];
    }
    __shared__ float r1[256], r2[256];
    r1[tid] = s1; r2[tid] = s2;
    __syncthreads();
    for (int o = 128; o > 0; o >>= 1) {
        if (tid < o) { r1[tid] += r1[tid + o]; r2[tid] += r2[tid + o]; }
        __syncthreads();
    }
    if (tid == 0) { g_partial[blockIdx.x] = r1[0]; g_partial[128 + blockIdx.x] = r2[0]; }
}

__global__ void finish_kernel(float* __restrict__ out, float invN, float invM) {
    __shared__ float sa[128], sb[128];
    int t = threadIdx.x;
    sa[t] = g_partial[t];
    sb[t] = g_partial[128 + t];
    __syncthreads();
    for (int o = 64; o > 0; o >>= 1) {
        if (t < o) { sa[t] += sa[t + o]; sb[t] += sb[t + o]; }
        __syncthreads();
    }
    if (t == 0) out[0] = 2.0f - sa[0] * invN - sb[0] * invM;
}

// ---------------- launch -----------------------------------------------------
extern "C" void kernel_launch(void* const* d_in, const int* in_sizes, int n_in,
                              void* d_out, int out_size) {
    const float* pred_pts = (const float*)d_in[0];
    const float* pred_nrm = (const float*)d_in[1];
    const float* gt_pts   = (const float*)d_in[2];
    const float* gt_nrm   = (const float*)d_in[3];
    float* out = (float*)d_out;

    const int N = in_sizes[0] / 3;   // 8192
    const int M = in_sizes[2] / 3;   // 32768
    const int mx = (N > M) ? N : M;

    prep_kernel<<<(mx + 255) / 256, 256>>>(pred_pts, gt_pts, N, M);

    dim3 g1(N / QPB, M / (2 * PAIRS));   // 32 x 16
    nn_kernel<0><<<g1, TPB>>>(pred_pts);

    dim3 g2(M / QPB, N / (2 * PAIRS));   // 128 x 4
    nn_kernel<1><<<g2, TPB>>>(gt_pts);

    loss_stage1<<<128, 256>>>(pred_nrm, gt_nrm, N, M);
    finish_kernel<<<1, 128>>>(out, 1.0f / (float)N, 1.0f / (float)M);
}